// round 3
// baseline (speedup 1.0000x reference)
#include <cuda_runtime.h>

// ---------------------------------------------------------------------------
// MeanAggregator: out[r, :] = mean over edges e with row_ids[e]==r of
//                 features[neigh_ids[e], :]   (row_ids sorted ascending)
//
// R3: single fused kernel. One warp per output row; warp finds its edge range
//     via binary search on sorted row_ids (lanes 0/1 search row / row+1).
//     LDG.128 feature gather (R1 layout — measured best), software-pipelined
//     index prefetch, __ldcg indices, __stcs output.
// ---------------------------------------------------------------------------

#define D_FEAT 128

// int64 detection: neigh_ids uniform-random in [0,100000) -> for int64 LE the
// odd 32-bit words are all zero; for int32 essentially never. Warp ballot.
__device__ __forceinline__ bool detect_is64(const void* neigh, int lane) {
    const unsigned* w = (const unsigned*)neigh;
    unsigned hiw = __ldg(&w[2 * lane + 1]);
    unsigned m = __ballot_sync(0xFFFFFFFFu, hiw == 0u);
    return __popc(m) >= 28;
}

template <typename IdxT>
__device__ __forceinline__ void run_row(const float4* __restrict__ feats,
                                        const IdxT* __restrict__ neigh,
                                        const IdxT* __restrict__ rows,
                                        int E, int row, int lane,
                                        float4* __restrict__ out) {
    // --- branchless-ish lower_bound: lanes with (lane&1)==0 search `row`,
    //     odd lanes search `row+1`; other lanes run redundantly (no divergence
    //     cost; the two distinct addresses per step are broadcast wavefronts).
    int key = row + (lane & 1);
    int pos = 0, n = E;
    while (n > 0) {
        int half = n >> 1;
        int v = (int)__ldg(rows + pos + half);
        if (v < key) { pos += half + 1; n -= half + 1; }
        else         { n = half; }
    }
    int lo = __shfl_sync(0xFFFFFFFFu, pos, 0);
    int hi = __shfl_sync(0xFFFFFFFFu, pos, 1);

    // --- gather + mean: lane owns float4 (16B); warp-wide LDG.128 = 512B row.
    float x = 0.f, y = 0.f, z = 0.f, w = 0.f;
    float x2 = 0.f, y2 = 0.f, z2 = 0.f, w2 = 0.f;

    int e = lo;
    int i0 = 0, i1 = 0, i2 = 0, i3 = 0;
    bool have = (e + 4 <= hi);
    if (have) {
        i0 = (int)__ldcg(neigh + e + 0);
        i1 = (int)__ldcg(neigh + e + 1);
        i2 = (int)__ldcg(neigh + e + 2);
        i3 = (int)__ldcg(neigh + e + 3);
    }
    while (have) {
        int c0 = i0, c1 = i1, c2 = i2, c3 = i3;
        int en = e + 4;
        bool haven = (en + 4 <= hi);
        if (haven) {  // prefetch next batch before consuming current feats
            i0 = (int)__ldcg(neigh + en + 0);
            i1 = (int)__ldcg(neigh + en + 1);
            i2 = (int)__ldcg(neigh + en + 2);
            i3 = (int)__ldcg(neigh + en + 3);
        }
        float4 a = __ldg(feats + (size_t)c0 * (D_FEAT / 4) + lane);
        float4 b = __ldg(feats + (size_t)c1 * (D_FEAT / 4) + lane);
        float4 c = __ldg(feats + (size_t)c2 * (D_FEAT / 4) + lane);
        float4 d = __ldg(feats + (size_t)c3 * (D_FEAT / 4) + lane);
        x  += a.x + b.x;  y  += a.y + b.y;  z  += a.z + b.z;  w  += a.w + b.w;
        x2 += c.x + d.x;  y2 += c.y + d.y;  z2 += c.z + d.z;  w2 += c.w + d.w;
        e = en; have = haven;
    }
    for (; e < hi; e++) {
        int c0 = (int)__ldcg(neigh + e);
        float4 a = __ldg(feats + (size_t)c0 * (D_FEAT / 4) + lane);
        x += a.x; y += a.y; z += a.z; w += a.w;
    }
    x += x2; y += y2; z += z2; w += w2;

    int cnt = hi - lo;
    float inv = 1.0f / (float)(cnt > 0 ? cnt : 1);
    float4 r4 = make_float4(x * inv, y * inv, z * inv, w * inv);
    __stcs(out + (size_t)row * (D_FEAT / 4) + lane, r4);
}

__global__ __launch_bounds__(256) void agg_fused_kernel(const float4* __restrict__ feats,
                                                        const void* __restrict__ neigh_v,
                                                        const void* __restrict__ rows_v,
                                                        int E, int nrows,
                                                        float4* __restrict__ out) {
    int gwarp = (blockIdx.x * blockDim.x + threadIdx.x) >> 5;
    int lane  = threadIdx.x & 31;
    if (gwarp >= nrows) return;
    bool is64 = detect_is64(neigh_v, lane);
    if (is64)
        run_row<long long>(feats, (const long long*)neigh_v,
                           (const long long*)rows_v, E, gwarp, lane, out);
    else
        run_row<int>(feats, (const int*)neigh_v,
                     (const int*)rows_v, E, gwarp, lane, out);
}

extern "C" void kernel_launch(void* const* d_in, const int* in_sizes, int n_in,
                              void* d_out, int out_size) {
    const float* feats = (const float*)d_in[0];
    const void*  neigh = d_in[1];
    const void*  rows  = d_in[2];
    int E     = in_sizes[1];
    int nrows = out_size / D_FEAT;

    int total_threads = nrows * 32;
    agg_fused_kernel<<<(total_threads + 255) / 256, 256>>>(
        (const float4*)feats, neigh, rows, E, nrows, (float4*)d_out);
}

// round 4
// speedup vs baseline: 1.5687x; 1.5687x over previous
#include <cuda_runtime.h>

// ---------------------------------------------------------------------------
// MeanAggregator: out[r, :] = mean over edges e with row_ids[e]==r of
//                 features[neigh_ids[e], :]   (row_ids sorted ascending)
//
// R4 = R1 agg (float4/LDG.128 layout, measured 53us = L1tex replay floor)
//    + R2 fused bounds kernel (detect + prefill + boundaries, one launch, ~3us)
//    + lane-parallel index fetch via shfl (fewer LSU issues in agg loop).
// ---------------------------------------------------------------------------

#define MAX_ROWS 131072
#define D_FEAT   128

__device__ int g_offsets[MAX_ROWS + 1];

// int64 detection: neigh_ids uniform-random in [0,100000) -> for int64 LE the
// odd 32-bit words are all zero; for int32 essentially never. Warp ballot.
__device__ __forceinline__ bool detect_is64(const void* neigh, int lane) {
    const unsigned* w = (const unsigned*)neigh;
    unsigned hiw = __ldg(&w[2 * lane + 1]);
    unsigned m = __ballot_sync(0xFFFFFFFFu, hiw == 0u);
    return __popc(m) >= 28;
}

template <typename IdxT>
__device__ __forceinline__ int row_at(const void* p, int i) {
    return (int)__ldg(((const IdxT*)p) + i);
}

// ---- segment boundaries from sorted row_ids (fused detect + trailing fill)
__global__ __launch_bounds__(256) void bounds_kernel(const void* __restrict__ rows_v,
                                                     const void* __restrict__ neigh_v,
                                                     int E, int nrows) {
    int i    = blockIdx.x * blockDim.x + threadIdx.x;
    int lane = threadIdx.x & 31;
    bool is64 = detect_is64(neigh_v, lane);
    if (i >= E) return;
    int r  = is64 ? row_at<long long>(rows_v, i) : row_at<int>(rows_v, i);
    int rp = (i == 0) ? -1
                      : (is64 ? row_at<long long>(rows_v, i - 1)
                              : row_at<int>(rows_v, i - 1));
    // all rows in (rp, r] start at edge i (covers gaps / leading empties)
    for (int q = rp + 1; q <= r; q++) g_offsets[q] = i;
    // trailing empty rows end at E
    if (i == E - 1) {
        for (int q = r + 1; q <= nrows; q++) g_offsets[q] = E;
    }
}

// ---- main gather+mean: one warp per row, lane owns float4 (LDG.128 layout).
// Index fetch: lanes 0..3 load the next 4 indices coalesced, broadcast by shfl.
template <typename IdxT>
__device__ __forceinline__ void aggregate_row(const float4* __restrict__ feats,
                                              const IdxT* __restrict__ neigh,
                                              int row, int lane, int lo, int hi,
                                              float4* __restrict__ out) {
    float x = 0.f, y = 0.f, z = 0.f, w = 0.f;
    float x2 = 0.f, y2 = 0.f, z2 = 0.f, w2 = 0.f;
    int e = lo;
    for (; e + 4 <= hi; e += 4) {
        int my = (lane < 4) ? (int)__ldg(neigh + e + lane) : 0;
        int n0 = __shfl_sync(0xFFFFFFFFu, my, 0);
        int n1 = __shfl_sync(0xFFFFFFFFu, my, 1);
        int n2 = __shfl_sync(0xFFFFFFFFu, my, 2);
        int n3 = __shfl_sync(0xFFFFFFFFu, my, 3);
        float4 a = __ldg(feats + (size_t)n0 * (D_FEAT / 4) + lane);
        float4 b = __ldg(feats + (size_t)n1 * (D_FEAT / 4) + lane);
        float4 c = __ldg(feats + (size_t)n2 * (D_FEAT / 4) + lane);
        float4 d = __ldg(feats + (size_t)n3 * (D_FEAT / 4) + lane);
        x  += a.x + b.x;  y  += a.y + b.y;  z  += a.z + b.z;  w  += a.w + b.w;
        x2 += c.x + d.x;  y2 += c.y + d.y;  z2 += c.z + d.z;  w2 += c.w + d.w;
    }
    for (; e < hi; e++) {
        int n = (int)__ldg(neigh + e);
        float4 a = __ldg(feats + (size_t)n * (D_FEAT / 4) + lane);
        x += a.x; y += a.y; z += a.z; w += a.w;
    }
    x += x2; y += y2; z += z2; w += w2;
    int cnt = hi - lo;
    float inv = 1.0f / (float)(cnt > 0 ? cnt : 1);
    float4 r4 = make_float4(x * inv, y * inv, z * inv, w * inv);
    out[(size_t)row * (D_FEAT / 4) + lane] = r4;
}

__global__ __launch_bounds__(256) void agg_kernel(const float4* __restrict__ feats,
                                                  const void* __restrict__ neigh_v,
                                                  int nrows,
                                                  float4* __restrict__ out) {
    int gwarp = (blockIdx.x * blockDim.x + threadIdx.x) >> 5;
    int lane  = threadIdx.x & 31;
    if (gwarp >= nrows) return;
    bool is64 = detect_is64(neigh_v, lane);
    int lo = g_offsets[gwarp];
    int hi = g_offsets[gwarp + 1];
    if (is64)
        aggregate_row<long long>(feats, (const long long*)neigh_v, gwarp, lane, lo, hi, out);
    else
        aggregate_row<int>(feats, (const int*)neigh_v, gwarp, lane, lo, hi, out);
}

extern "C" void kernel_launch(void* const* d_in, const int* in_sizes, int n_in,
                              void* d_out, int out_size) {
    const float* feats = (const float*)d_in[0];
    const void*  neigh = d_in[1];
    const void*  rows  = d_in[2];
    int E     = in_sizes[1];
    int nrows = out_size / D_FEAT;

    bounds_kernel<<<(E + 255) / 256, 256>>>(rows, neigh, E, nrows);

    int total_threads = nrows * 32;
    agg_kernel<<<(total_threads + 255) / 256, 256>>>(
        (const float4*)feats, neigh, nrows, (float4*)d_out);
}